// round 1
// baseline (speedup 1.0000x reference)
#include <cuda_runtime.h>

// ---------------------------------------------------------------------------
// PrecisionPredictorLoss:
//   eff  = mean((P - T)^2)                     over B*d*d elements
//   tr_p[b], tr_t[b] = trace of first m=min(B,32) matrices
//   rank = sum_{i<j} margin(tr) / (m*(m-1)/2)
//   total = eff + 0.1 * rank
// Shapes fixed by problem: B=4096, d=64.
// ---------------------------------------------------------------------------

#define NBLK 1184          // 148 SMs * 8 blocks
#define TPB  256

__device__ float g_partials[NBLK];

__device__ __forceinline__ float warp_sum(float v) {
    #pragma unroll
    for (int o = 16; o; o >>= 1) v += __shfl_down_sync(0xffffffffu, v, o);
    return v;
}

__global__ void __launch_bounds__(TPB) sqdiff_reduce(
    const float4* __restrict__ p, const float4* __restrict__ t, int n4)
{
    float acc = 0.0f;
    for (int i = blockIdx.x * TPB + threadIdx.x; i < n4; i += gridDim.x * TPB) {
        float4 a = p[i];
        float4 b = t[i];
        float d0 = a.x - b.x, d1 = a.y - b.y, d2 = a.z - b.z, d3 = a.w - b.w;
        acc = fmaf(d0, d0, acc);
        acc = fmaf(d1, d1, acc);
        acc = fmaf(d2, d2, acc);
        acc = fmaf(d3, d3, acc);
    }
    __shared__ float s[TPB / 32];
    acc = warp_sum(acc);
    if ((threadIdx.x & 31) == 0) s[threadIdx.x >> 5] = acc;
    __syncthreads();
    if (threadIdx.x < 32) {
        float v = (threadIdx.x < TPB / 32) ? s[threadIdx.x] : 0.0f;
        #pragma unroll
        for (int o = 4; o; o >>= 1) v += __shfl_down_sync(0xffffffffu, v, o);
        if (threadIdx.x == 0) g_partials[blockIdx.x] = v;
    }
}

__global__ void __launch_bounds__(1024) finalize_kernel(
    const float* __restrict__ pred, const float* __restrict__ tru,
    float* __restrict__ out, long long n_total, int B, int out_size)
{
    __shared__ float tr_p[32], tr_t[32];
    __shared__ float red[32];
    __shared__ float s_sumsq, s_rank;

    const int tid  = threadIdx.x;
    const int warp = tid >> 5;
    const int lane = tid & 31;
    const int m    = (B < 32) ? B : 32;

    // ---- 1) reduce the NBLK per-block partial sums of squared diffs ----
    float s = 0.0f;
    for (int i = tid; i < NBLK; i += 1024) s += g_partials[i];
    s = warp_sum(s);
    if (lane == 0) red[warp] = s;
    __syncthreads();
    if (tid < 32) {
        float v = red[tid];
        #pragma unroll
        for (int o = 16; o; o >>= 1) v += __shfl_down_sync(0xffffffffu, v, o);
        if (tid == 0) s_sumsq = v;
    }

    // ---- 2) traces of the first m matrices (warp b handles batch b) ----
    if (warp < m) {
        const long long base = (long long)warp * 64 * 64;
        float tp = pred[base + (long long)lane * 65] + pred[base + (long long)(lane + 32) * 65];
        float tt = tru [base + (long long)lane * 65] + tru [base + (long long)(lane + 32) * 65];
        tp = warp_sum(tp);
        tt = warp_sum(tt);
        if (lane == 0) { tr_p[warp] = tp; tr_t[warp] = tt; }
    }
    __syncthreads();

    // ---- 3) pairwise rank loss over upper triangle (i < j) ----
    float c = 0.0f;
    {
        int i = warp;     // 0..31
        int j = lane;     // 0..31
        if (i < j && j < m) {
            float dt = tr_t[i] - tr_t[j];
            float dp = tr_p[i] - tr_p[j];
            if (dt > 0.0f)      c = fmaxf(-dp + 0.1f, 0.0f);
            else if (dt < 0.0f) c = fmaxf( dp + 0.1f, 0.0f);
        }
    }
    __syncthreads();           // red[] reuse
    c = warp_sum(c);
    if (lane == 0) red[warp] = c;
    __syncthreads();
    if (tid < 32) {
        float v = red[tid];
        #pragma unroll
        for (int o = 16; o; o >>= 1) v += __shfl_down_sync(0xffffffffu, v, o);
        if (tid == 0) s_rank = v;
    }
    __syncthreads();

    // ---- 4) combine and write outputs ----
    if (tid == 0) {
        float eff = s_sumsq / (float)n_total;
        int n_pairs = m * (m - 1) / 2;
        float rank = (m > 1) ? (s_rank / (float)n_pairs) : 0.0f;
        float total = eff + 0.1f * rank;
        out[0] = total;
        if (out_size > 1) out[1] = eff;
        if (out_size > 2) out[2] = rank;
    }
}

extern "C" void kernel_launch(void* const* d_in, const int* in_sizes, int n_in,
                              void* d_out, int out_size)
{
    const float* pred = (const float*)d_in[0];
    const float* tru  = (const float*)d_in[1];
    float* out = (float*)d_out;

    long long n = (long long)in_sizes[0];   // B * 64 * 64
    int n4 = (int)(n / 4);
    int B  = (int)(n / (64 * 64));

    sqdiff_reduce<<<NBLK, TPB>>>((const float4*)pred, (const float4*)tru, n4);
    finalize_kernel<<<1, 1024>>>(pred, tru, out, n, B, out_size);
}

// round 2
// speedup vs baseline: 1.0779x; 1.0779x over previous
#include <cuda_runtime.h>

// ---------------------------------------------------------------------------
// PrecisionPredictorLoss:
//   eff  = mean((P - T)^2)                 over B*d*d elements
//   tr_p[b], tr_t[b] = trace of first m=min(B,32) matrices (d=64)
//   rank = sum_{i<j} margin(tr) / (m*(m-1)/2)
//   total = eff + 0.1 * rank
// Shapes fixed by problem: B=4096, d=64.
//
// Structure: kernel 1 = NBLK streaming blocks (sq-diff partial sums) plus ONE
// extra block that computes the 32 traces (overlapped with the 20us stream).
// kernel 2 = tiny finalize, reads only L2-resident partials/traces.
// ---------------------------------------------------------------------------

#define NBLK 1184          // 148 SMs * 8 streaming blocks
#define TPB  256

__device__ float g_partials[NBLK];
__device__ float g_tr_p[32];
__device__ float g_tr_t[32];

__device__ __forceinline__ float warp_sum(float v) {
    #pragma unroll
    for (int o = 16; o; o >>= 1) v += __shfl_down_sync(0xffffffffu, v, o);
    return v;
}

__global__ void __launch_bounds__(TPB) main_pass(
    const float4* __restrict__ p, const float4* __restrict__ t,
    int n4, int B)
{
    if (blockIdx.x == NBLK) {
        // ---- trace block: 8 warps, each handles 4 of the first m matrices ----
        const float* pf = (const float*)p;
        const float* tf = (const float*)t;
        const int warp = threadIdx.x >> 5;
        const int lane = threadIdx.x & 31;
        const int m = (B < 32) ? B : 32;
        #pragma unroll
        for (int k = 0; k < 4; k++) {
            int b = warp * 4 + k;              // matrix index 0..31
            if (b >= m) break;
            const long long base = (long long)b * 64 * 64;
            // diag stride = 65 floats; lanes cover rows [lane] and [lane+32]
            float tp = pf[base + (long long)lane * 65]
                     + pf[base + (long long)(lane + 32) * 65];
            float tt = tf[base + (long long)lane * 65]
                     + tf[base + (long long)(lane + 32) * 65];
            tp = warp_sum(tp);
            tt = warp_sum(tt);
            if (lane == 0) { g_tr_p[b] = tp; g_tr_t[b] = tt; }
        }
        return;
    }

    // ---- streaming squared-diff partial reduction ----
    float acc = 0.0f;
    const int stride = NBLK * TPB;
    #pragma unroll 4
    for (int i = blockIdx.x * TPB + threadIdx.x; i < n4; i += stride) {
        float4 a = p[i];
        float4 b = t[i];
        float d0 = a.x - b.x, d1 = a.y - b.y, d2 = a.z - b.z, d3 = a.w - b.w;
        acc = fmaf(d0, d0, acc);
        acc = fmaf(d1, d1, acc);
        acc = fmaf(d2, d2, acc);
        acc = fmaf(d3, d3, acc);
    }
    __shared__ float s[TPB / 32];
    acc = warp_sum(acc);
    if ((threadIdx.x & 31) == 0) s[threadIdx.x >> 5] = acc;
    __syncthreads();
    if (threadIdx.x < 32) {
        float v = (threadIdx.x < TPB / 32) ? s[threadIdx.x] : 0.0f;
        #pragma unroll
        for (int o = 4; o; o >>= 1) v += __shfl_down_sync(0xffffffffu, v, o);
        if (threadIdx.x == 0) g_partials[blockIdx.x] = v;
    }
}

__global__ void __launch_bounds__(1024) finalize_kernel(
    float* __restrict__ out, long long n_total, int B, int out_size)
{
    __shared__ float red[32];
    __shared__ float s_sumsq;

    const int tid  = threadIdx.x;
    const int warp = tid >> 5;
    const int lane = tid & 31;
    const int m    = (B < 32) ? B : 32;

    // ---- 1) reduce the NBLK per-block partials (L2-resident) ----
    float s = 0.0f;
    for (int i = tid; i < NBLK; i += 1024) s += g_partials[i];
    s = warp_sum(s);
    if (lane == 0) red[warp] = s;
    __syncthreads();
    if (tid < 32) {
        float v = red[tid];
        #pragma unroll
        for (int o = 16; o; o >>= 1) v += __shfl_down_sync(0xffffffffu, v, o);
        if (tid == 0) s_sumsq = v;
    }
    __syncthreads();

    // ---- 2) pairwise rank loss over upper triangle (i < j), warp=i lane=j ----
    float c = 0.0f;
    if (warp < m && lane < m && warp < lane) {
        float dt = g_tr_t[warp] - g_tr_t[lane];
        float dp = g_tr_p[warp] - g_tr_p[lane];
        if (dt > 0.0f)      c = fmaxf(-dp + 0.1f, 0.0f);
        else if (dt < 0.0f) c = fmaxf( dp + 0.1f, 0.0f);
    }
    c = warp_sum(c);
    if (lane == 0) red[warp] = c;
    __syncthreads();

    // ---- 3) combine and write outputs ----
    if (tid == 0) {
        float rank_total = 0.0f;
        #pragma unroll
        for (int i = 0; i < 32; i++) rank_total += red[i];
        float eff = s_sumsq / (float)n_total;
        int n_pairs = m * (m - 1) / 2;
        float rank = (m > 1) ? (rank_total / (float)n_pairs) : 0.0f;
        out[0] = eff + 0.1f * rank;
        if (out_size > 1) out[1] = eff;
        if (out_size > 2) out[2] = rank;
    }
}

extern "C" void kernel_launch(void* const* d_in, const int* in_sizes, int n_in,
                              void* d_out, int out_size)
{
    const float* pred = (const float*)d_in[0];
    const float* tru  = (const float*)d_in[1];
    float* out = (float*)d_out;

    long long n = (long long)in_sizes[0];   // B * 64 * 64
    int n4 = (int)(n / 4);
    int B  = (int)(n / (64 * 64));

    main_pass<<<NBLK + 1, TPB>>>((const float4*)pred, (const float4*)tru, n4, B);
    finalize_kernel<<<1, 1024>>>(out, n, B, out_size);
}